// round 2
// baseline (speedup 1.0000x reference)
#include <cuda_runtime.h>
#include <cuda_bf16.h>

#ifndef LR
#define LR 0.01f
#endif

// C == 4 fast path: 4 rows per thread, front-batched streaming loads.
// u <- a*u + c applied 100 times == 25 applications of the exact 4-step
// affine map (a4, c4), where a = 1 - 2*LR*q, c = -LR*p.
__global__ void diffmpc2_c4_v2_kernel(const float4* __restrict__ Qv,
                                      const float4* __restrict__ Pv,
                                      const float4* __restrict__ Uv,
                                      float4* __restrict__ OUTv,
                                      int B, int row_len4 /* row_len/4 */) {
    constexpr int ROWS = 4;
    int t = blockIdx.x * blockDim.x + threadIdx.x;
    int stride = gridDim.x * blockDim.x;

    int r[ROWS];
    bool ok[ROWS];
    float4 q[ROWS], p[ROWS], u[ROWS];

    // Front-batch all loads: 12 independent LDG.128 in flight per thread.
#pragma unroll
    for (int i = 0; i < ROWS; i++) {
        r[i] = t + i * stride;
        ok[i] = (r[i] < B);
    }
#pragma unroll
    for (int i = 0; i < ROWS; i++) {
        if (ok[i]) q[i] = __ldcs(&Qv[(size_t)r[i] * row_len4 + (row_len4 - 1)]);
    }
#pragma unroll
    for (int i = 0; i < ROWS; i++) {
        if (ok[i]) p[i] = __ldcs(&Pv[(size_t)r[i] * row_len4 + (row_len4 - 1)]);
    }
#pragma unroll
    for (int i = 0; i < ROWS; i++) {
        if (ok[i]) u[i] = __ldcs(&Uv[r[i]]);
    }

#pragma unroll
    for (int i = 0; i < ROWS; i++) {
        if (!ok[i]) continue;
        float4 a, c;
        a.x = fmaf(-2.0f * LR, q[i].x, 1.0f);
        a.y = fmaf(-2.0f * LR, q[i].y, 1.0f);
        a.z = fmaf(-2.0f * LR, q[i].z, 1.0f);
        a.w = fmaf(-2.0f * LR, q[i].w, 1.0f);
        c.x = -LR * p[i].x; c.y = -LR * p[i].y;
        c.z = -LR * p[i].z; c.w = -LR * p[i].w;

        float4 a2, c2;
        a2.x = a.x * a.x; c2.x = fmaf(a.x, c.x, c.x);
        a2.y = a.y * a.y; c2.y = fmaf(a.y, c.y, c.y);
        a2.z = a.z * a.z; c2.z = fmaf(a.z, c.z, c.z);
        a2.w = a.w * a.w; c2.w = fmaf(a.w, c.w, c.w);

        float4 a4, c4;
        a4.x = a2.x * a2.x; c4.x = fmaf(a2.x, c2.x, c2.x);
        a4.y = a2.y * a2.y; c4.y = fmaf(a2.y, c2.y, c2.y);
        a4.z = a2.z * a2.z; c4.z = fmaf(a2.z, c2.z, c2.z);
        a4.w = a2.w * a2.w; c4.w = fmaf(a2.w, c2.w, c2.w);

#pragma unroll
        for (int s = 0; s < 25; s++) {
            u[i].x = fmaf(a4.x, u[i].x, c4.x);
            u[i].y = fmaf(a4.y, u[i].y, c4.y);
            u[i].z = fmaf(a4.z, u[i].z, c4.z);
            u[i].w = fmaf(a4.w, u[i].w, c4.w);
        }
    }

#pragma unroll
    for (int i = 0; i < ROWS; i++) {
        if (ok[i]) __stcs(&OUTv[r[i]], u[i]);
    }
}

// Generic fallback: one thread per (b, j) element, same composed math.
__global__ void diffmpc2_gen_kernel(const float* __restrict__ Q,
                                    const float* __restrict__ P,
                                    const float* __restrict__ U0,
                                    float* __restrict__ OUT,
                                    int B, int S, int C) {
    int e = blockIdx.x * blockDim.x + threadIdx.x;
    if (e >= B * C) return;
    int b = e / C;
    int j = e - b * C;
    size_t off = (size_t)b * (size_t)(S + C) + (size_t)(S + j);

    float q = Q[off];
    float p = P[off];
    float u = U0[e];

    float a = fmaf(-2.0f * LR, q, 1.0f);
    float c = -LR * p;
    float a2 = a * a,   c2 = fmaf(a, c, c);
    float a4 = a2 * a2, c4 = fmaf(a2, c2, c2);
#pragma unroll
    for (int i = 0; i < 25; i++) u = fmaf(a4, u, c4);
    OUT[e] = u;
}

extern "C" void kernel_launch(void* const* d_in, const int* in_sizes, int n_in,
                              void* d_out, int out_size) {
    // inputs: x_init [B,S] (unused), Q [B,S+C], p [B,S+C], u_init [B,C]
    const float* Q  = (const float*)d_in[1];
    const float* P  = (const float*)d_in[2];
    const float* U0 = (const float*)d_in[3];
    float* OUT = (float*)d_out;

    int C = 4;
    int B = out_size / C;
    int S = (B > 0) ? in_sizes[0] / B : 0;
    int row_len = S + C;

    bool c4_ok = (B * C == out_size) && (B > 0) &&
                 ((size_t)B * row_len == (size_t)in_sizes[1]) &&
                 (B * S == in_sizes[0]) && (row_len % 4 == 0);

    if (c4_ok) {
        constexpr int ROWS = 4;
        int threads = 256;
        int blocks = (B + threads * ROWS - 1) / (threads * ROWS);
        diffmpc2_c4_v2_kernel<<<blocks, threads>>>(
            (const float4*)Q, (const float4*)P, (const float4*)U0,
            (float4*)OUT, B, row_len / 4);
    } else {
        int Bc = 0, Sc = 0, Cc = 0;
        for (int c = 1; c <= 64; c++) {
            if (out_size % c) continue;
            int b = out_size / c;
            if (b == 0 || in_sizes[0] % b) continue;
            int s = in_sizes[0] / b;
            if ((size_t)b * (size_t)(s + c) == (size_t)in_sizes[1]) {
                Bc = b; Sc = s; Cc = c; break;
            }
        }
        int total = out_size;
        int threads = 256;
        int blocks = (total + threads - 1) / threads;
        diffmpc2_gen_kernel<<<blocks, threads>>>(Q, P, U0, OUT, Bc, Sc, Cc);
    }
}

// round 3
// speedup vs baseline: 1.0348x; 1.0348x over previous
#include <cuda_runtime.h>
#include <cuda_bf16.h>

#ifndef LR
#define LR 0.01f
#endif

// C == 4 fast path: one thread per batch row (the round-1 winner shape),
// plus streaming cache hints. u <- a*u + c applied 100 times, composed into
// 25 applications of the exact 4-step affine map (a4, c4),
// a = 1 - 2*LR*q, c = -LR*p.
__global__ __launch_bounds__(256)
void diffmpc2_c4_v3_kernel(const float4* __restrict__ Qv,
                           const float4* __restrict__ Pv,
                           const float4* __restrict__ Uv,
                           float4* __restrict__ OUTv,
                           int B, int row_len4 /* row_len/4 */) {
    int b = blockIdx.x * blockDim.x + threadIdx.x;
    if (b >= B) return;

    size_t tail = (size_t)b * (size_t)row_len4 + (size_t)(row_len4 - 1);
    const float4 q = __ldcs(&Qv[tail]);
    const float4 p = __ldcs(&Pv[tail]);
    float4 u = __ldcs(&Uv[b]);

    float4 a, c;
    a.x = fmaf(-2.0f * LR, q.x, 1.0f);
    a.y = fmaf(-2.0f * LR, q.y, 1.0f);
    a.z = fmaf(-2.0f * LR, q.z, 1.0f);
    a.w = fmaf(-2.0f * LR, q.w, 1.0f);
    c.x = -LR * p.x; c.y = -LR * p.y; c.z = -LR * p.z; c.w = -LR * p.w;

    // Compose 2 steps: (a,c) -> (a^2, a*c + c). Twice -> exact 4-step map.
    float4 a2, c2;
    a2.x = a.x * a.x; c2.x = fmaf(a.x, c.x, c.x);
    a2.y = a.y * a.y; c2.y = fmaf(a.y, c.y, c.y);
    a2.z = a.z * a.z; c2.z = fmaf(a.z, c.z, c.z);
    a2.w = a.w * a.w; c2.w = fmaf(a.w, c.w, c.w);

    float4 a4, c4;
    a4.x = a2.x * a2.x; c4.x = fmaf(a2.x, c2.x, c2.x);
    a4.y = a2.y * a2.y; c4.y = fmaf(a2.y, c2.y, c2.y);
    a4.z = a2.z * a2.z; c4.z = fmaf(a2.z, c2.z, c2.z);
    a4.w = a2.w * a2.w; c4.w = fmaf(a2.w, c2.w, c2.w);

    // 25 x 4-step map = 100 steps. 4 independent FMA chains per thread.
#pragma unroll
    for (int i = 0; i < 25; i++) {
        u.x = fmaf(a4.x, u.x, c4.x);
        u.y = fmaf(a4.y, u.y, c4.y);
        u.z = fmaf(a4.z, u.z, c4.z);
        u.w = fmaf(a4.w, u.w, c4.w);
    }

    __stcs(&OUTv[b], u);
}

// Generic fallback: one thread per (b, j) element, same composed math.
__global__ void diffmpc2_gen_kernel(const float* __restrict__ Q,
                                    const float* __restrict__ P,
                                    const float* __restrict__ U0,
                                    float* __restrict__ OUT,
                                    int B, int S, int C) {
    int e = blockIdx.x * blockDim.x + threadIdx.x;
    if (e >= B * C) return;
    int b = e / C;
    int j = e - b * C;
    size_t off = (size_t)b * (size_t)(S + C) + (size_t)(S + j);

    float q = Q[off];
    float p = P[off];
    float u = U0[e];

    float a = fmaf(-2.0f * LR, q, 1.0f);
    float c = -LR * p;
    float a2 = a * a,   c2 = fmaf(a, c, c);
    float a4 = a2 * a2, c4 = fmaf(a2, c2, c2);
#pragma unroll
    for (int i = 0; i < 25; i++) u = fmaf(a4, u, c4);
    OUT[e] = u;
}

extern "C" void kernel_launch(void* const* d_in, const int* in_sizes, int n_in,
                              void* d_out, int out_size) {
    // inputs: x_init [B,S] (unused), Q [B,S+C], p [B,S+C], u_init [B,C]
    const float* Q  = (const float*)d_in[1];
    const float* P  = (const float*)d_in[2];
    const float* U0 = (const float*)d_in[3];
    float* OUT = (float*)d_out;

    int C = 4;
    int B = out_size / C;
    int S = (B > 0) ? in_sizes[0] / B : 0;
    int row_len = S + C;

    bool c4_ok = (B * C == out_size) && (B > 0) &&
                 ((size_t)B * row_len == (size_t)in_sizes[1]) &&
                 (B * S == in_sizes[0]) && (row_len % 4 == 0);

    if (c4_ok) {
        int threads = 256;
        int blocks = (B + threads - 1) / threads;
        diffmpc2_c4_v3_kernel<<<blocks, threads>>>(
            (const float4*)Q, (const float4*)P, (const float4*)U0,
            (float4*)OUT, B, row_len / 4);
    } else {
        int Bc = 0, Sc = 0, Cc = 0;
        for (int c = 1; c <= 64; c++) {
            if (out_size % c) continue;
            int b = out_size / c;
            if (b == 0 || in_sizes[0] % b) continue;
            int s = in_sizes[0] / b;
            if ((size_t)b * (size_t)(s + c) == (size_t)in_sizes[1]) {
                Bc = b; Sc = s; Cc = c; break;
            }
        }
        int total = out_size;
        int threads = 256;
        int blocks = (total + threads - 1) / threads;
        diffmpc2_gen_kernel<<<blocks, threads>>>(Q, P, U0, OUT, Bc, Sc, Cc);
    }
}

// round 4
// speedup vs baseline: 1.1110x; 1.0736x over previous
#include <cuda_runtime.h>
#include <cuda_bf16.h>

#ifndef LR
#define LR 0.01f
#endif

// Exact 100-step map: a = 1-2*LR*q, c = -LR*p; compose to (a4, c4), apply 25x.
__device__ __forceinline__ float4 run100(const float4 q, const float4 p, float4 u) {
    float4 a, c;
    a.x = fmaf(-2.0f * LR, q.x, 1.0f);
    a.y = fmaf(-2.0f * LR, q.y, 1.0f);
    a.z = fmaf(-2.0f * LR, q.z, 1.0f);
    a.w = fmaf(-2.0f * LR, q.w, 1.0f);
    c.x = -LR * p.x; c.y = -LR * p.y; c.z = -LR * p.z; c.w = -LR * p.w;

    float4 a2, c2;
    a2.x = a.x * a.x; c2.x = fmaf(a.x, c.x, c.x);
    a2.y = a.y * a.y; c2.y = fmaf(a.y, c.y, c.y);
    a2.z = a.z * a.z; c2.z = fmaf(a.z, c.z, c.z);
    a2.w = a.w * a.w; c2.w = fmaf(a.w, c.w, c.w);

    float4 a4, c4;
    a4.x = a2.x * a2.x; c4.x = fmaf(a2.x, c2.x, c2.x);
    a4.y = a2.y * a2.y; c4.y = fmaf(a2.y, c2.y, c2.y);
    a4.z = a2.z * a2.z; c4.z = fmaf(a2.z, c2.z, c2.z);
    a4.w = a2.w * a2.w; c4.w = fmaf(a2.w, c2.w, c2.w);

#pragma unroll
    for (int i = 0; i < 25; i++) {
        u.x = fmaf(a4.x, u.x, c4.x);
        u.y = fmaf(a4.y, u.y, c4.y);
        u.z = fmaf(a4.z, u.z, c4.z);
        u.w = fmaf(a4.w, u.w, c4.w);
    }
    return u;
}

// Single-wave persistent kernel: each thread owns ITERS rows (grid-stride),
// with next-iteration loads issued before the current iteration's compute
// (software pipeline, 2 iterations live -> moderate regs, high occupancy,
// loads continuously in flight for the warp's whole lifetime).
template <int ITERS>
__global__ __launch_bounds__(256)
void diffmpc2_c4_pipe_kernel(const float4* __restrict__ Qv,
                             const float4* __restrict__ Pv,
                             const float4* __restrict__ Uv,
                             float4* __restrict__ OUTv,
                             int row_len4) {
    const int stride = gridDim.x * blockDim.x;
    int idx = blockIdx.x * blockDim.x + threadIdx.x;

    // Prologue loads (iteration 0).
    size_t tail = (size_t)idx * (size_t)row_len4 + (size_t)(row_len4 - 1);
    float4 q = __ldcs(&Qv[tail]);
    float4 p = __ldcs(&Pv[tail]);
    float4 u = __ldcs(&Uv[idx]);

#pragma unroll
    for (int i = 0; i < ITERS; i++) {
        float4 qn, pn, un;
        int idx_next = idx + stride;
        if (i + 1 < ITERS) {
            size_t tn = (size_t)idx_next * (size_t)row_len4 + (size_t)(row_len4 - 1);
            qn = __ldcs(&Qv[tn]);
            pn = __ldcs(&Pv[tn]);
            un = __ldcs(&Uv[idx_next]);
        }

        __stcs(&OUTv[idx], run100(q, p, u));

        q = qn; p = pn; u = un;
        idx = idx_next;
    }
}

// Simple 1-row/thread version (fallback when B doesn't divide evenly).
__global__ __launch_bounds__(256)
void diffmpc2_c4_v3_kernel(const float4* __restrict__ Qv,
                           const float4* __restrict__ Pv,
                           const float4* __restrict__ Uv,
                           float4* __restrict__ OUTv,
                           int B, int row_len4) {
    int b = blockIdx.x * blockDim.x + threadIdx.x;
    if (b >= B) return;
    size_t tail = (size_t)b * (size_t)row_len4 + (size_t)(row_len4 - 1);
    float4 q = __ldcs(&Qv[tail]);
    float4 p = __ldcs(&Pv[tail]);
    float4 u = __ldcs(&Uv[b]);
    __stcs(&OUTv[b], run100(q, p, u));
}

// Generic fallback: one thread per (b, j) element, same composed math.
__global__ void diffmpc2_gen_kernel(const float* __restrict__ Q,
                                    const float* __restrict__ P,
                                    const float* __restrict__ U0,
                                    float* __restrict__ OUT,
                                    int B, int S, int C) {
    int e = blockIdx.x * blockDim.x + threadIdx.x;
    if (e >= B * C) return;
    int b = e / C;
    int j = e - b * C;
    size_t off = (size_t)b * (size_t)(S + C) + (size_t)(S + j);

    float q = Q[off];
    float p = P[off];
    float u = U0[e];

    float a = fmaf(-2.0f * LR, q, 1.0f);
    float c = -LR * p;
    float a2 = a * a,   c2 = fmaf(a, c, c);
    float a4 = a2 * a2, c4 = fmaf(a2, c2, c2);
#pragma unroll
    for (int i = 0; i < 25; i++) u = fmaf(a4, u, c4);
    OUT[e] = u;
}

extern "C" void kernel_launch(void* const* d_in, const int* in_sizes, int n_in,
                              void* d_out, int out_size) {
    // inputs: x_init [B,S] (unused), Q [B,S+C], p [B,S+C], u_init [B,C]
    const float* Q  = (const float*)d_in[1];
    const float* P  = (const float*)d_in[2];
    const float* U0 = (const float*)d_in[3];
    float* OUT = (float*)d_out;

    int C = 4;
    int B = out_size / C;
    int S = (B > 0) ? in_sizes[0] / B : 0;
    int row_len = S + C;

    bool c4_ok = (B * C == out_size) && (B > 0) &&
                 ((size_t)B * row_len == (size_t)in_sizes[1]) &&
                 (B * S == in_sizes[0]) && (row_len % 4 == 0);

    if (c4_ok) {
        constexpr int ITERS = 4;
        const int threads = 256;
        if (B % (threads * ITERS) == 0) {
            int blocks = B / (threads * ITERS);  // 1024 for B=1M
            diffmpc2_c4_pipe_kernel<ITERS><<<blocks, threads>>>(
                (const float4*)Q, (const float4*)P, (const float4*)U0,
                (float4*)OUT, row_len / 4);
        } else {
            int blocks = (B + threads - 1) / threads;
            diffmpc2_c4_v3_kernel<<<blocks, threads>>>(
                (const float4*)Q, (const float4*)P, (const float4*)U0,
                (float4*)OUT, B, row_len / 4);
        }
    } else {
        int Bc = 0, Sc = 0, Cc = 0;
        for (int c = 1; c <= 64; c++) {
            if (out_size % c) continue;
            int b = out_size / c;
            if (b == 0 || in_sizes[0] % b) continue;
            int s = in_sizes[0] / b;
            if ((size_t)b * (size_t)(s + c) == (size_t)in_sizes[1]) {
                Bc = b; Sc = s; Cc = c; break;
            }
        }
        int total = out_size;
        int threads = 256;
        int blocks = (total + threads - 1) / threads;
        diffmpc2_gen_kernel<<<blocks, threads>>>(Q, P, U0, OUT, Bc, Sc, Cc);
    }
}